// round 1
// baseline (speedup 1.0000x reference)
#include <cuda_runtime.h>
#include <math.h>

#define NN      50000
#define EE      1600000
#define HD      128
#define BGRAPH  512
#define CLS     10

// ---------------- scratch (device globals; no allocs allowed) ----------------
__device__ float  g_degb[NN];          // sum of edge weights per dst (no self loop)
__device__ int    g_cnt[NN];           // in-degree counts
__device__ int    g_rowptr[NN + 1];    // CSR row pointers (by dst)
__device__ int    g_woff[NN];          // scatter write cursors
__device__ float  g_dinv1[NN];         // (deg+1)^-1/2
__device__ float  g_dinv2[NN];         // (deg+2)^-1/2
__device__ float2 g_e1[EE];            // (src_as_float_bits, norm1)  layer 1
__device__ float2 g_e2[EE];            // (src_as_float_bits, norm )  layers 2,3
__device__ float  g_t[(size_t)NN * HD];  // GEMM output / agg input
__device__ float  g_h[(size_t)NN * HD];  // agg output / next GEMM input
__device__ float  g_psum[BGRAPH * HD];
__device__ float  g_pcnt[BGRAPH];

// ---------------- kernels ----------------------------------------------------

__global__ void k_zero(int n) {
    int i = blockIdx.x * blockDim.x + threadIdx.x;
    int stride = gridDim.x * blockDim.x;
    for (int j = i; j < n; j += stride) { g_degb[j] = 0.f; g_cnt[j] = 0; }
    for (int j = i; j < BGRAPH * HD; j += stride) g_psum[j] = 0.f;
    for (int j = i; j < BGRAPH; j += stride) g_pcnt[j] = 0.f;
}

// pass 1 over edges: degree (weighted) + in-degree count histogram
__global__ void k_deg(const int* __restrict__ dst, const float* __restrict__ ew, int E) {
    int i = blockIdx.x * blockDim.x + threadIdx.x;
    if (i >= E) return;
    int d = dst[i];
    atomicAdd(&g_degb[d], ew[i]);
    atomicAdd(&g_cnt[d], 1);
}

__global__ void k_dinv(int n) {
    int i = blockIdx.x * blockDim.x + threadIdx.x;
    if (i >= n) return;
    float db = g_degb[i];
    g_dinv1[i] = rsqrtf(db + 1.0f);
    g_dinv2[i] = rsqrtf(db + 2.0f);
}

// single-block exclusive scan of g_cnt -> g_rowptr / g_woff
__global__ void k_scan(int n, int E) {
    __shared__ int s[1024];
    int tid = threadIdx.x;
    int chunk = (n + 1023) / 1024;
    int beg = tid * chunk;
    int end = min(beg + chunk, n);
    int sum = 0;
    for (int i = beg; i < end; i++) sum += g_cnt[i];
    s[tid] = sum;
    __syncthreads();
    for (int off = 1; off < 1024; off <<= 1) {
        int v = (tid >= off) ? s[tid - off] : 0;
        __syncthreads();
        s[tid] += v;
        __syncthreads();
    }
    int run = (tid == 0) ? 0 : s[tid - 1];
    for (int i = beg; i < end; i++) {
        int c = g_cnt[i];
        g_rowptr[i] = run;
        g_woff[i]   = run;
        run += c;
    }
    if (tid == 0) g_rowptr[n] = E;
}

// pass 2: scatter edges into CSR buckets with both norm variants
__global__ void k_scatter(const int* __restrict__ src, const int* __restrict__ dst,
                          const float* __restrict__ ew, int E) {
    int e = blockIdx.x * blockDim.x + threadIdx.x;
    if (e >= E) return;
    int s = src[e];
    int d = dst[e];
    float w = ew[e];
    int pos = atomicAdd(&g_woff[d], 1);
    float n1 = g_dinv2[s] * w * g_dinv2[d];
    float n2 = g_dinv1[s] * w * g_dinv1[d];
    g_e1[pos] = make_float2(__int_as_float(s), n1);
    g_e2[pos] = make_float2(__int_as_float(s), n2);
}

// SGEMM: C[M,128] = A[M,128] @ B[128,128], fp32. BM=BN=128, BK=8, 8x8 microtile.
__global__ void __launch_bounds__(256) k_gemm(const float* __restrict__ A,
                                              const float* __restrict__ B,
                                              float* __restrict__ C, int M) {
    __shared__ float As[8][128];   // transposed: As[k][m]
    __shared__ float Bs[8][128];
    int tid = threadIdx.x;
    int block_row = blockIdx.x * 128;
    int tx = tid & 15;      // 0..15 -> col group
    int ty = tid >> 4;      // 0..15 -> row group
    float acc[8][8];
#pragma unroll
    for (int i = 0; i < 8; i++)
#pragma unroll
        for (int j = 0; j < 8; j++) acc[i][j] = 0.f;

    int a_row = tid >> 1;          // 0..127
    int a_col = (tid & 1) * 4;     // 0 or 4
    int b_row = tid >> 5;          // 0..7
    int b_col = (tid & 31) * 4;    // 0..124

    for (int k0 = 0; k0 < 128; k0 += 8) {
        int gr = block_row + a_row;
        float4 av = (gr < M) ? *(const float4*)(A + (size_t)gr * HD + k0 + a_col)
                             : make_float4(0.f, 0.f, 0.f, 0.f);
        As[a_col + 0][a_row] = av.x;
        As[a_col + 1][a_row] = av.y;
        As[a_col + 2][a_row] = av.z;
        As[a_col + 3][a_row] = av.w;
        *(float4*)&Bs[b_row][b_col] = *(const float4*)(B + (size_t)(k0 + b_row) * HD + b_col);
        __syncthreads();
#pragma unroll
        for (int k = 0; k < 8; k++) {
            float a[8], b[8];
            *(float4*)&a[0] = *(const float4*)&As[k][ty * 8];
            *(float4*)&a[4] = *(const float4*)&As[k][ty * 8 + 4];
            *(float4*)&b[0] = *(const float4*)&Bs[k][tx * 8];
            *(float4*)&b[4] = *(const float4*)&Bs[k][tx * 8 + 4];
#pragma unroll
            for (int i = 0; i < 8; i++)
#pragma unroll
                for (int j = 0; j < 8; j++) acc[i][j] += a[i] * b[j];
        }
        __syncthreads();
    }
#pragma unroll
    for (int i = 0; i < 8; i++) {
        int gr = block_row + ty * 8 + i;
        if (gr < M) {
            *(float4*)(C + (size_t)gr * HD + tx * 8)     = make_float4(acc[i][0], acc[i][1], acc[i][2], acc[i][3]);
            *(float4*)(C + (size_t)gr * HD + tx * 8 + 4) = make_float4(acc[i][4], acc[i][5], acc[i][6], acc[i][7]);
        }
    }
}

// aggregation: warp per dst node, register accumulation, no output atomics.
// out[i] = sum_e nrm[e]*t[col[e]] + fill/(degb[i]+fill) * t[i] + bias ; optional relu
__global__ void __launch_bounds__(256) k_agg(const float* __restrict__ t,
                                             const float2* __restrict__ ed,
                                             const float* __restrict__ bias,
                                             float fill, int relu,
                                             float* __restrict__ out, int n) {
    int warp = (blockIdx.x * blockDim.x + threadIdx.x) >> 5;
    int lane = threadIdx.x & 31;
    if (warp >= n) return;
    int beg = g_rowptr[warp];
    int end = g_rowptr[warp + 1];
    float4 acc = make_float4(0.f, 0.f, 0.f, 0.f);
    for (int e = beg; e < end; e++) {
        float2 cw = __ldg(&ed[e]);
        int c = __float_as_int(cw.x);
        float w = cw.y;
        float4 v = *(const float4*)(t + (size_t)c * HD + lane * 4);
        acc.x += w * v.x; acc.y += w * v.y; acc.z += w * v.z; acc.w += w * v.w;
    }
    float sn = fill / (g_degb[warp] + fill);
    float4 v = *(const float4*)(t + (size_t)warp * HD + lane * 4);
    acc.x += sn * v.x; acc.y += sn * v.y; acc.z += sn * v.z; acc.w += sn * v.w;
    float4 b4 = *(const float4*)(bias + lane * 4);
    acc.x += b4.x; acc.y += b4.y; acc.z += b4.z; acc.w += b4.w;
    if (relu) {
        acc.x = fmaxf(acc.x, 0.f); acc.y = fmaxf(acc.y, 0.f);
        acc.z = fmaxf(acc.z, 0.f); acc.w = fmaxf(acc.w, 0.f);
    }
    *(float4*)(out + (size_t)warp * HD + lane * 4) = acc;
}

// mean-pool accumulate: warp per node, vectorized red to graph sums
__global__ void __launch_bounds__(256) k_pool(const float* __restrict__ h,
                                              const int* __restrict__ batch, int n) {
    int warp = (blockIdx.x * blockDim.x + threadIdx.x) >> 5;
    int lane = threadIdx.x & 31;
    if (warp >= n) return;
    int b = batch[warp];
    float4 v = *(const float4*)(h + (size_t)warp * HD + lane * 4);
    float* p = &g_psum[b * HD + lane * 4];
    asm volatile("red.global.add.v4.f32 [%0], {%1,%2,%3,%4};"
                 :: "l"(p), "f"(v.x), "f"(v.y), "f"(v.z), "f"(v.w) : "memory");
    if (lane == 0) atomicAdd(&g_pcnt[b], 1.0f);
}

// head: out[b][c] = (sum_k psum[b][k]*Wlin[k][c]) / max(cnt,1) + blin[c]
__global__ void k_final(const float* __restrict__ Wlin, const float* __restrict__ blin,
                        float* __restrict__ out) {
    int idx = blockIdx.x * blockDim.x + threadIdx.x;
    if (idx >= BGRAPH * CLS) return;
    int b = idx / CLS;
    int c = idx % CLS;
    float acc = 0.f;
#pragma unroll 8
    for (int k = 0; k < HD; k++) acc += g_psum[b * HD + k] * Wlin[k * CLS + c];
    float cnt = fmaxf(g_pcnt[b], 1.0f);
    out[idx] = acc / cnt + blin[c];
}

// ---------------- launch ------------------------------------------------------
extern "C" void kernel_launch(void* const* d_in, const int* in_sizes, int n_in,
                              void* d_out, int out_size) {
    const float* x    = (const float*)d_in[0];
    const int*   eidx = (const int*)d_in[1];
    const int*   batch= (const int*)d_in[2];
    const float* ew   = (const float*)d_in[3];
    const float* W1   = (const float*)d_in[4];
    const float* b1   = (const float*)d_in[5];
    const float* W2   = (const float*)d_in[6];
    const float* b2   = (const float*)d_in[7];
    const float* W3   = (const float*)d_in[8];
    const float* b3   = (const float*)d_in[9];
    const float* Wlin = (const float*)d_in[10];
    const float* blin = (const float*)d_in[11];
    float* out = (float*)d_out;

    int N = in_sizes[0] / HD;
    int E = in_sizes[1] / 2;
    const int* src = eidx;
    const int* dst = eidx + E;

    float* t = nullptr; float* h = nullptr;
    float2* e1 = nullptr; float2* e2 = nullptr;
    cudaGetSymbolAddress((void**)&t,  g_t);
    cudaGetSymbolAddress((void**)&h,  g_h);
    cudaGetSymbolAddress((void**)&e1, g_e1);
    cudaGetSymbolAddress((void**)&e2, g_e2);

    int eb = (E + 255) / 256;
    int nb = (N + 255) / 256;
    int wb = (N * 32 + 255) / 256;   // warp-per-node grids
    int gb = (N + 127) / 128;        // gemm grid

    k_zero<<<256, 256>>>(N);
    k_deg<<<eb, 256>>>(dst, ew, E);
    k_dinv<<<nb, 256>>>(N);
    k_scan<<<1, 1024>>>(N, E);
    k_scatter<<<eb, 256>>>(src, dst, ew, E);

    // layer 1: relu(A1 (x@W1) + b1), fill=2
    k_gemm<<<gb, 256>>>(x, W1, t, N);
    k_agg<<<wb, 256>>>(t, e1, b1, 2.0f, 1, h, N);
    // layer 2: relu(A (h@W2) + b2), fill=1
    k_gemm<<<gb, 256>>>(h, W2, t, N);
    k_agg<<<wb, 256>>>(t, e2, b2, 1.0f, 1, h, N);
    // layer 3: A (h@W3) + b3, fill=1
    k_gemm<<<gb, 256>>>(h, W3, t, N);
    k_agg<<<wb, 256>>>(t, e2, b3, 1.0f, 0, h, N);

    k_pool<<<wb, 256>>>(h, batch, N);
    k_final<<<(BGRAPH * CLS + 127) / 128, 128>>>(Wlin, blin, out);
}

// round 2
// speedup vs baseline: 1.1952x; 1.1952x over previous
#include <cuda_runtime.h>
#include <cuda_fp16.h>
#include <math.h>

#define NN      50000
#define EE      1600000
#define HD      128
#define BGRAPH  512
#define CLS     10
#define SCAN_B  ((NN + 255) / 256)   // 196 partial blocks

// ---------------- scratch (device globals; no allocs allowed) ----------------
__device__ float  g_degb[NN];          // sum of edge weights per dst (no self loop)
__device__ int    g_cnt[NN];           // in-degree counts
__device__ int    g_rowptr[NN + 1];    // CSR row pointers (by dst)
__device__ int    g_woff[NN];          // scatter write cursors
__device__ float  g_dinv1[NN];         // (deg+1)^-1/2
__device__ float  g_dinv2[NN];         // (deg+2)^-1/2
__device__ int    g_part[SCAN_B];      // scan partials
__device__ int    g_partscan[SCAN_B];  // exclusive-scanned partials
__device__ float2 g_e1[EE];            // (src_bits, norm1)  layer 1
__device__ float2 g_e2[EE];            // (src_bits, norm )  layers 2,3
__device__ __half g_th[(size_t)NN * HD]; // GEMM output (fp16) / agg gather input
__device__ float  g_h[(size_t)NN * HD];  // agg output (fp32) / next GEMM input
__device__ float  g_psum[BGRAPH * HD];
__device__ float  g_pcnt[BGRAPH];

// ---------------- kernels ----------------------------------------------------

__global__ void k_zero(int n) {
    int i = blockIdx.x * blockDim.x + threadIdx.x;
    int stride = gridDim.x * blockDim.x;
    for (int j = i; j < n; j += stride) { g_degb[j] = 0.f; g_cnt[j] = 0; }
    for (int j = i; j < BGRAPH * HD; j += stride) g_psum[j] = 0.f;
    for (int j = i; j < BGRAPH; j += stride) g_pcnt[j] = 0.f;
}

// pass 1 over edges: weighted degree + in-degree count histogram
__global__ void k_deg(const int* __restrict__ dst, const float* __restrict__ ew, int E) {
    int i = blockIdx.x * blockDim.x + threadIdx.x;
    if (i >= E) return;
    int d = dst[i];
    atomicAdd(&g_degb[d], ew[i]);
    atomicAdd(&g_cnt[d], 1);
}

__global__ void k_dinv(int n) {
    int i = blockIdx.x * blockDim.x + threadIdx.x;
    if (i >= n) return;
    float db = g_degb[i];
    g_dinv1[i] = rsqrtf(db + 1.0f);
    g_dinv2[i] = rsqrtf(db + 2.0f);
}

// --- parallel 3-phase exclusive scan of g_cnt -> g_rowptr / g_woff ---
__global__ void k_scan_partial(int n) {
    __shared__ int s[256];
    int i = blockIdx.x * 256 + threadIdx.x;
    s[threadIdx.x] = (i < n) ? g_cnt[i] : 0;
    __syncthreads();
    for (int off = 128; off > 0; off >>= 1) {
        if (threadIdx.x < off) s[threadIdx.x] += s[threadIdx.x + off];
        __syncthreads();
    }
    if (threadIdx.x == 0) g_part[blockIdx.x] = s[0];
}

__global__ void k_scan_top(int nblocks) {
    __shared__ int s[256];
    int tid = threadIdx.x;
    int v = (tid < nblocks) ? g_part[tid] : 0;
    s[tid] = v;
    __syncthreads();
    for (int off = 1; off < 256; off <<= 1) {
        int u = (tid >= off) ? s[tid - off] : 0;
        __syncthreads();
        s[tid] += u;
        __syncthreads();
    }
    if (tid < nblocks) g_partscan[tid] = s[tid] - v;   // exclusive
}

__global__ void k_scan_write(int n, int E) {
    __shared__ int s[256];
    int tid = threadIdx.x;
    int i = blockIdx.x * 256 + tid;
    int c = (i < n) ? g_cnt[i] : 0;
    s[tid] = c;
    __syncthreads();
    for (int off = 1; off < 256; off <<= 1) {
        int u = (tid >= off) ? s[tid - off] : 0;
        __syncthreads();
        s[tid] += u;
        __syncthreads();
    }
    if (i < n) {
        int p = g_partscan[blockIdx.x] + s[tid] - c;   // exclusive within block
        g_rowptr[i] = p;
        g_woff[i]   = p;
    }
    if (blockIdx.x == 0 && tid == 0) g_rowptr[n] = E;
}

// pass 2: scatter edges into CSR buckets with both norm variants
__global__ void k_scatter(const int* __restrict__ src, const int* __restrict__ dst,
                          const float* __restrict__ ew, int E) {
    int e = blockIdx.x * blockDim.x + threadIdx.x;
    if (e >= E) return;
    int s = src[e];
    int d = dst[e];
    float w = ew[e];
    int pos = atomicAdd(&g_woff[d], 1);
    float n1 = g_dinv2[s] * w * g_dinv2[d];
    float n2 = g_dinv1[s] * w * g_dinv1[d];
    g_e1[pos] = make_float2(__int_as_float(s), n1);
    g_e2[pos] = make_float2(__int_as_float(s), n2);
}

// SGEMM: C[M,128](fp16) = A[M,128] @ B[128,128], fp32 math. 128x128 tile, 8x8 micro.
__global__ void __launch_bounds__(256) k_gemm(const float* __restrict__ A,
                                              const float* __restrict__ B,
                                              __half* __restrict__ C, int M) {
    __shared__ float As[8][128];
    __shared__ float Bs[8][128];
    int tid = threadIdx.x;
    int block_row = blockIdx.x * 128;
    int tx = tid & 15;
    int ty = tid >> 4;
    float acc[8][8];
#pragma unroll
    for (int i = 0; i < 8; i++)
#pragma unroll
        for (int j = 0; j < 8; j++) acc[i][j] = 0.f;

    int a_row = tid >> 1;
    int a_col = (tid & 1) * 4;
    int b_row = tid >> 5;
    int b_col = (tid & 31) * 4;

    for (int k0 = 0; k0 < 128; k0 += 8) {
        int gr = block_row + a_row;
        float4 av = (gr < M) ? *(const float4*)(A + (size_t)gr * HD + k0 + a_col)
                             : make_float4(0.f, 0.f, 0.f, 0.f);
        As[a_col + 0][a_row] = av.x;
        As[a_col + 1][a_row] = av.y;
        As[a_col + 2][a_row] = av.z;
        As[a_col + 3][a_row] = av.w;
        *(float4*)&Bs[b_row][b_col] = *(const float4*)(B + (size_t)(k0 + b_row) * HD + b_col);
        __syncthreads();
#pragma unroll
        for (int k = 0; k < 8; k++) {
            float a[8], b[8];
            *(float4*)&a[0] = *(const float4*)&As[k][ty * 8];
            *(float4*)&a[4] = *(const float4*)&As[k][ty * 8 + 4];
            *(float4*)&b[0] = *(const float4*)&Bs[k][tx * 8];
            *(float4*)&b[4] = *(const float4*)&Bs[k][tx * 8 + 4];
#pragma unroll
            for (int i = 0; i < 8; i++)
#pragma unroll
                for (int j = 0; j < 8; j++) acc[i][j] += a[i] * b[j];
        }
        __syncthreads();
    }
#pragma unroll
    for (int i = 0; i < 8; i++) {
        int gr = block_row + ty * 8 + i;
        if (gr < M) {
            union { __half2 h2[4]; uint4 u; } pk;
            pk.h2[0] = __floats2half2_rn(acc[i][0], acc[i][1]);
            pk.h2[1] = __floats2half2_rn(acc[i][2], acc[i][3]);
            pk.h2[2] = __floats2half2_rn(acc[i][4], acc[i][5]);
            pk.h2[3] = __floats2half2_rn(acc[i][6], acc[i][7]);
            *(uint4*)(C + (size_t)gr * HD + tx * 8) = pk.u;
        }
    }
}

// aggregation: warp per dst node, fp16 gathers, fp32 accumulate, no output atomics.
__global__ void __launch_bounds__(256) k_agg(const __half* __restrict__ t,
                                             const float2* __restrict__ ed,
                                             const float* __restrict__ bias,
                                             float fill, int relu,
                                             float* __restrict__ out, int n) {
    int warp = (blockIdx.x * blockDim.x + threadIdx.x) >> 5;
    int lane = threadIdx.x & 31;
    if (warp >= n) return;
    int beg = g_rowptr[warp];
    int end = g_rowptr[warp + 1];
    float4 acc0 = make_float4(0.f, 0.f, 0.f, 0.f);
    float4 acc1 = make_float4(0.f, 0.f, 0.f, 0.f);
    int e = beg;
    for (; e + 1 < end; e += 2) {
        float2 cw0 = __ldg(&ed[e]);
        float2 cw1 = __ldg(&ed[e + 1]);
        int c0 = __float_as_int(cw0.x);
        int c1 = __float_as_int(cw1.x);
        uint2 r0 = __ldg((const uint2*)(t + (size_t)c0 * HD) + lane);
        uint2 r1 = __ldg((const uint2*)(t + (size_t)c1 * HD) + lane);
        float2 a0 = __half22float2(*(__half2*)&r0.x);
        float2 b0 = __half22float2(*(__half2*)&r0.y);
        float2 a1 = __half22float2(*(__half2*)&r1.x);
        float2 b1 = __half22float2(*(__half2*)&r1.y);
        acc0.x += cw0.y * a0.x; acc0.y += cw0.y * a0.y;
        acc0.z += cw0.y * b0.x; acc0.w += cw0.y * b0.y;
        acc1.x += cw1.y * a1.x; acc1.y += cw1.y * a1.y;
        acc1.z += cw1.y * b1.x; acc1.w += cw1.y * b1.y;
    }
    if (e < end) {
        float2 cw = __ldg(&ed[e]);
        int c = __float_as_int(cw.x);
        uint2 r = __ldg((const uint2*)(t + (size_t)c * HD) + lane);
        float2 a = __half22float2(*(__half2*)&r.x);
        float2 b = __half22float2(*(__half2*)&r.y);
        acc0.x += cw.y * a.x; acc0.y += cw.y * a.y;
        acc0.z += cw.y * b.x; acc0.w += cw.y * b.y;
    }
    acc0.x += acc1.x; acc0.y += acc1.y; acc0.z += acc1.z; acc0.w += acc1.w;
    // self-loop + bias
    float sn = fill / (g_degb[warp] + fill);
    uint2 rs = __ldg((const uint2*)(t + (size_t)warp * HD) + lane);
    float2 sa = __half22float2(*(__half2*)&rs.x);
    float2 sb = __half22float2(*(__half2*)&rs.y);
    acc0.x += sn * sa.x; acc0.y += sn * sa.y;
    acc0.z += sn * sb.x; acc0.w += sn * sb.y;
    float4 b4 = *(const float4*)(bias + lane * 4);
    acc0.x += b4.x; acc0.y += b4.y; acc0.z += b4.z; acc0.w += b4.w;
    if (relu) {
        acc0.x = fmaxf(acc0.x, 0.f); acc0.y = fmaxf(acc0.y, 0.f);
        acc0.z = fmaxf(acc0.z, 0.f); acc0.w = fmaxf(acc0.w, 0.f);
    }
    *(float4*)(out + (size_t)warp * HD + lane * 4) = acc0;
}

// mean-pool accumulate: warp per node, vectorized red to graph sums
__global__ void __launch_bounds__(256) k_pool(const float* __restrict__ h,
                                              const int* __restrict__ batch, int n) {
    int warp = (blockIdx.x * blockDim.x + threadIdx.x) >> 5;
    int lane = threadIdx.x & 31;
    if (warp >= n) return;
    int b = batch[warp];
    float4 v = *(const float4*)(h + (size_t)warp * HD + lane * 4);
    float* p = &g_psum[b * HD + lane * 4];
    asm volatile("red.global.add.v4.f32 [%0], {%1,%2,%3,%4};"
                 :: "l"(p), "f"(v.x), "f"(v.y), "f"(v.z), "f"(v.w) : "memory");
    if (lane == 0) atomicAdd(&g_pcnt[b], 1.0f);
}

// head: out[b][c] = (sum_k psum[b][k]*Wlin[k][c]) / max(cnt,1) + blin[c]
__global__ void k_final(const float* __restrict__ Wlin, const float* __restrict__ blin,
                        float* __restrict__ out) {
    int idx = blockIdx.x * blockDim.x + threadIdx.x;
    if (idx >= BGRAPH * CLS) return;
    int b = idx / CLS;
    int c = idx % CLS;
    float acc = 0.f;
#pragma unroll 8
    for (int k = 0; k < HD; k++) acc += g_psum[b * HD + k] * Wlin[k * CLS + c];
    float cnt = fmaxf(g_pcnt[b], 1.0f);
    out[idx] = acc / cnt + blin[c];
}

// ---------------- launch ------------------------------------------------------
extern "C" void kernel_launch(void* const* d_in, const int* in_sizes, int n_in,
                              void* d_out, int out_size) {
    const float* x    = (const float*)d_in[0];
    const int*   eidx = (const int*)d_in[1];
    const int*   batch= (const int*)d_in[2];
    const float* ew   = (const float*)d_in[3];
    const float* W1   = (const float*)d_in[4];
    const float* b1   = (const float*)d_in[5];
    const float* W2   = (const float*)d_in[6];
    const float* b2   = (const float*)d_in[7];
    const float* W3   = (const float*)d_in[8];
    const float* b3   = (const float*)d_in[9];
    const float* Wlin = (const float*)d_in[10];
    const float* blin = (const float*)d_in[11];
    float* out = (float*)d_out;

    int N = in_sizes[0] / HD;
    int E = in_sizes[1] / 2;
    const int* src = eidx;
    const int* dst = eidx + E;

    __half* th = nullptr; float* h = nullptr;
    float2* e1 = nullptr; float2* e2 = nullptr;
    cudaGetSymbolAddress((void**)&th, g_th);
    cudaGetSymbolAddress((void**)&h,  g_h);
    cudaGetSymbolAddress((void**)&e1, g_e1);
    cudaGetSymbolAddress((void**)&e2, g_e2);

    int eb = (E + 255) / 256;
    int nb = (N + 255) / 256;
    int wb = (N * 32 + 255) / 256;   // warp-per-node grids
    int gb = (N + 127) / 128;        // gemm grid
    int sb = (N + 255) / 256;        // scan blocks

    k_zero<<<256, 256>>>(N);
    k_deg<<<eb, 256>>>(dst, ew, E);
    k_dinv<<<nb, 256>>>(N);
    k_scan_partial<<<sb, 256>>>(N);
    k_scan_top<<<1, 256>>>(sb);
    k_scan_write<<<sb, 256>>>(N, E);
    k_scatter<<<eb, 256>>>(src, dst, ew, E);

    // layer 1: relu(A1 (x@W1) + b1), fill=2
    k_gemm<<<gb, 256>>>(x, W1, th, N);
    k_agg<<<wb, 256>>>(th, e1, b1, 2.0f, 1, h, N);
    // layer 2: relu(A (h@W2) + b2), fill=1
    k_gemm<<<gb, 256>>>(h, W2, th, N);
    k_agg<<<wb, 256>>>(th, e2, b2, 1.0f, 1, h, N);
    // layer 3: A (h@W3) + b3, fill=1
    k_gemm<<<gb, 256>>>(h, W3, th, N);
    k_agg<<<wb, 256>>>(th, e2, b3, 1.0f, 0, h, N);

    k_pool<<<wb, 256>>>(h, batch, N);
    k_final<<<(BGRAPH * CLS + 127) / 128, 128>>>(Wlin, blin, out);
}

// round 3
// speedup vs baseline: 1.6443x; 1.3758x over previous
#include <cuda_runtime.h>
#include <cuda_fp16.h>
#include <math.h>
#include <stdint.h>

#define NN      50000
#define EE      1600000
#define HD      128
#define BGRAPH  512
#define CLS     10
#define SCAN_B  ((NN + 255) / 256)

// ---------------- scratch (device globals; no allocs allowed) ----------------
__device__ float  g_degb[NN];
__device__ int    g_cnt[NN];
__device__ int    g_rowptr[NN + 1];
__device__ int    g_woff[NN];
__device__ float  g_dinv1[NN];
__device__ float  g_dinv2[NN];
__device__ int    g_part[SCAN_B];
__device__ int    g_partscan[SCAN_B];
__device__ float2 g_e1[EE];              // (src_bits, norm1)  layer 1
__device__ float2 g_e2[EE];              // (src_bits, norm )  layers 2,3
__device__ __half g_th[(size_t)NN * HD]; // GEMM output (fp16) -> agg gather input
__device__ __half g_hh[(size_t)NN * HD]; // agg output (fp16)  -> next GEMM input
__device__ float  g_h[(size_t)NN * HD];  // layer-3 agg output (fp32) -> pool
__device__ uint2  g_bperm[8 * 16 * 32];  // W in mma B-fragment layout
__device__ float  g_psum[BGRAPH * HD];
__device__ float  g_pcnt[BGRAPH];

// ---------------- preprocessing ----------------------------------------------

__global__ void k_zero(int n) {
    int i = blockIdx.x * blockDim.x + threadIdx.x;
    int stride = gridDim.x * blockDim.x;
    for (int j = i; j < n; j += stride) { g_degb[j] = 0.f; g_cnt[j] = 0; }
    for (int j = i; j < BGRAPH * HD; j += stride) g_psum[j] = 0.f;
    for (int j = i; j < BGRAPH; j += stride) g_pcnt[j] = 0.f;
}

__global__ void k_deg(const int* __restrict__ dst, const float* __restrict__ ew, int E) {
    int i = blockIdx.x * blockDim.x + threadIdx.x;
    if (i >= E) return;
    int d = dst[i];
    atomicAdd(&g_degb[d], ew[i]);
    atomicAdd(&g_cnt[d], 1);
}

__global__ void k_dinv(int n) {
    int i = blockIdx.x * blockDim.x + threadIdx.x;
    if (i >= n) return;
    float db = g_degb[i];
    g_dinv1[i] = rsqrtf(db + 1.0f);
    g_dinv2[i] = rsqrtf(db + 2.0f);
}

__global__ void k_scan_partial(int n) {
    __shared__ int s[256];
    int i = blockIdx.x * 256 + threadIdx.x;
    s[threadIdx.x] = (i < n) ? g_cnt[i] : 0;
    __syncthreads();
    for (int off = 128; off > 0; off >>= 1) {
        if (threadIdx.x < off) s[threadIdx.x] += s[threadIdx.x + off];
        __syncthreads();
    }
    if (threadIdx.x == 0) g_part[blockIdx.x] = s[0];
}

__global__ void k_scan_top(int nblocks) {
    __shared__ int s[256];
    int tid = threadIdx.x;
    int v = (tid < nblocks) ? g_part[tid] : 0;
    s[tid] = v;
    __syncthreads();
    for (int off = 1; off < 256; off <<= 1) {
        int u = (tid >= off) ? s[tid - off] : 0;
        __syncthreads();
        s[tid] += u;
        __syncthreads();
    }
    if (tid < nblocks) g_partscan[tid] = s[tid] - v;
}

__global__ void k_scan_write(int n, int E) {
    __shared__ int s[256];
    int tid = threadIdx.x;
    int i = blockIdx.x * 256 + tid;
    int c = (i < n) ? g_cnt[i] : 0;
    s[tid] = c;
    __syncthreads();
    for (int off = 1; off < 256; off <<= 1) {
        int u = (tid >= off) ? s[tid - off] : 0;
        __syncthreads();
        s[tid] += u;
        __syncthreads();
    }
    if (i < n) {
        int p = g_partscan[blockIdx.x] + s[tid] - c;
        g_rowptr[i] = p;
        g_woff[i]   = p;
    }
    if (blockIdx.x == 0 && tid == 0) g_rowptr[n] = E;
}

__global__ void k_scatter(const int* __restrict__ src, const int* __restrict__ dst,
                          const float* __restrict__ ew, int E) {
    int e = blockIdx.x * blockDim.x + threadIdx.x;
    if (e >= E) return;
    int s = src[e];
    int d = dst[e];
    float w = ew[e];
    int pos = atomicAdd(&g_woff[d], 1);
    float n1 = g_dinv2[s] * w * g_dinv2[d];
    float n2 = g_dinv1[s] * w * g_dinv1[d];
    g_e1[pos] = make_float2(__int_as_float(s), n1);
    g_e2[pos] = make_float2(__int_as_float(s), n2);
}

// ---------------- tensor-core GEMM --------------------------------------------
// Pre-permute W [128x128] fp32 into per-lane m16n8k16 B-fragment layout.
// idx -> (kt 0..7, nt 0..15, lane 0..31); b0={W[k][n],W[k+1][n]}, b1={W[k+8][n],W[k+9][n]}
__global__ void k_bperm(const float* __restrict__ W) {
    int idx = blockIdx.x * blockDim.x + threadIdx.x;
    if (idx >= 8 * 16 * 32) return;
    int lane = idx & 31;
    int nt = (idx >> 5) & 15;
    int kt = idx >> 9;
    int k = kt * 16 + ((lane & 3) << 1);
    int n = nt * 8 + (lane >> 2);
    __half2 r0 = __floats2half2_rn(W[k * HD + n],       W[(k + 1) * HD + n]);
    __half2 r1 = __floats2half2_rn(W[(k + 8) * HD + n], W[(k + 9) * HD + n]);
    g_bperm[idx] = make_uint2(*(uint32_t*)&r0, *(uint32_t*)&r1);
}

__device__ __forceinline__ uint32_t ldA(const float* A, int r, int kc, int M) {
    if (r >= M) return 0u;
    float2 v = *(const float2*)(A + (size_t)r * HD + kc);
    __half2 h = __floats2half2_rn(v.x, v.y);
    return *(uint32_t*)&h;
}
__device__ __forceinline__ uint32_t ldA(const __half* A, int r, int kc, int M) {
    if (r >= M) return 0u;
    return *(const uint32_t*)(A + (size_t)r * HD + kc);
}

// C[M,128](fp16) = A[M,128] @ Wperm.  128-row block, 8 warps (4 m-groups x 2 n-groups),
// no smem, no syncs. A fragments straight from gmem (L2-resident), B from g_bperm (L1).
template <typename AT>
__global__ void __launch_bounds__(256) k_gemm_tc(const AT* __restrict__ A,
                                                 __half* __restrict__ C, int M) {
    int lane = threadIdx.x & 31;
    int wid  = threadIdx.x >> 5;
    int wm   = wid & 3;            // m group: 32 rows
    int wn   = wid >> 2;           // n group: 64 cols
    int base = blockIdx.x * 128 + wm * 32 + (lane >> 2);
    int kc0  = (lane & 3) << 1;

    float acc[2][8][4];
#pragma unroll
    for (int mt = 0; mt < 2; mt++)
#pragma unroll
        for (int nt = 0; nt < 8; nt++)
#pragma unroll
            for (int i = 0; i < 4; i++) acc[mt][nt][i] = 0.f;

#pragma unroll
    for (int kt = 0; kt < 8; kt++) {
        int kc = kt * 16 + kc0;
        uint32_t a[2][4];
#pragma unroll
        for (int mt = 0; mt < 2; mt++) {
            int r = base + mt * 16;
            a[mt][0] = ldA(A, r,     kc,     M);
            a[mt][1] = ldA(A, r + 8, kc,     M);
            a[mt][2] = ldA(A, r,     kc + 8, M);
            a[mt][3] = ldA(A, r + 8, kc + 8, M);
        }
#pragma unroll
        for (int nt = 0; nt < 8; nt++) {
            uint2 b = g_bperm[(size_t)((kt * 16 + wn * 8 + nt) * 32 + lane)];
#pragma unroll
            for (int mt = 0; mt < 2; mt++) {
                asm volatile(
                    "mma.sync.aligned.m16n8k16.row.col.f32.f16.f16.f32 "
                    "{%0,%1,%2,%3}, {%4,%5,%6,%7}, {%8,%9}, {%0,%1,%2,%3};"
                    : "+f"(acc[mt][nt][0]), "+f"(acc[mt][nt][1]),
                      "+f"(acc[mt][nt][2]), "+f"(acc[mt][nt][3])
                    : "r"(a[mt][0]), "r"(a[mt][1]), "r"(a[mt][2]), "r"(a[mt][3]),
                      "r"(b.x), "r"(b.y));
            }
        }
    }

#pragma unroll
    for (int mt = 0; mt < 2; mt++) {
        int r = base + mt * 16;
#pragma unroll
        for (int nt = 0; nt < 8; nt++) {
            int n = wn * 64 + nt * 8 + ((lane & 3) << 1);
            if (r < M) {
                __half2 h = __floats2half2_rn(acc[mt][nt][0], acc[mt][nt][1]);
                *(uint32_t*)(C + (size_t)r * HD + n) = *(uint32_t*)&h;
            }
            if (r + 8 < M) {
                __half2 h = __floats2half2_rn(acc[mt][nt][2], acc[mt][nt][3]);
                *(uint32_t*)(C + (size_t)(r + 8) * HD + n) = *(uint32_t*)&h;
            }
        }
    }
}

// ---------------- aggregation --------------------------------------------------
__device__ __forceinline__ void store_out(float* o, size_t off, float4 v) {
    *(float4*)(o + off) = v;
}
__device__ __forceinline__ void store_out(__half* o, size_t off, float4 v) {
    __half2 h0 = __floats2half2_rn(v.x, v.y);
    __half2 h1 = __floats2half2_rn(v.z, v.w);
    *(uint2*)(o + off) = make_uint2(*(uint32_t*)&h0, *(uint32_t*)&h1);
}

// warp per dst node, fp16 gathers, fp32 accumulate.
template <typename OUT>
__global__ void __launch_bounds__(256) k_agg(const __half* __restrict__ t,
                                             const float2* __restrict__ ed,
                                             const float* __restrict__ bias,
                                             float fill, int relu,
                                             OUT* __restrict__ out, int n) {
    int warp = (blockIdx.x * blockDim.x + threadIdx.x) >> 5;
    int lane = threadIdx.x & 31;
    if (warp >= n) return;
    int beg = g_rowptr[warp];
    int end = g_rowptr[warp + 1];
    float4 acc0 = make_float4(0.f, 0.f, 0.f, 0.f);
    float4 acc1 = make_float4(0.f, 0.f, 0.f, 0.f);
    int e = beg;
    for (; e + 1 < end; e += 2) {
        float2 cw0 = __ldg(&ed[e]);
        float2 cw1 = __ldg(&ed[e + 1]);
        int c0 = __float_as_int(cw0.x);
        int c1 = __float_as_int(cw1.x);
        uint2 r0 = __ldg((const uint2*)(t + (size_t)c0 * HD) + lane);
        uint2 r1 = __ldg((const uint2*)(t + (size_t)c1 * HD) + lane);
        float2 a0 = __half22float2(*(__half2*)&r0.x);
        float2 b0 = __half22float2(*(__half2*)&r0.y);
        float2 a1 = __half22float2(*(__half2*)&r1.x);
        float2 b1 = __half22float2(*(__half2*)&r1.y);
        acc0.x += cw0.y * a0.x; acc0.y += cw0.y * a0.y;
        acc0.z += cw0.y * b0.x; acc0.w += cw0.y * b0.y;
        acc1.x += cw1.y * a1.x; acc1.y += cw1.y * a1.y;
        acc1.z += cw1.y * b1.x; acc1.w += cw1.y * b1.y;
    }
    if (e < end) {
        float2 cw = __ldg(&ed[e]);
        int c = __float_as_int(cw.x);
        uint2 r = __ldg((const uint2*)(t + (size_t)c * HD) + lane);
        float2 a = __half22float2(*(__half2*)&r.x);
        float2 b = __half22float2(*(__half2*)&r.y);
        acc0.x += cw.y * a.x; acc0.y += cw.y * a.y;
        acc0.z += cw.y * b.x; acc0.w += cw.y * b.y;
    }
    acc0.x += acc1.x; acc0.y += acc1.y; acc0.z += acc1.z; acc0.w += acc1.w;
    float sn = fill / (g_degb[warp] + fill);
    uint2 rs = __ldg((const uint2*)(t + (size_t)warp * HD) + lane);
    float2 sa = __half22float2(*(__half2*)&rs.x);
    float2 sb = __half22float2(*(__half2*)&rs.y);
    acc0.x += sn * sa.x; acc0.y += sn * sa.y;
    acc0.z += sn * sb.x; acc0.w += sn * sb.y;
    float4 b4 = *(const float4*)(bias + lane * 4);
    acc0.x += b4.x; acc0.y += b4.y; acc0.z += b4.z; acc0.w += b4.w;
    if (relu) {
        acc0.x = fmaxf(acc0.x, 0.f); acc0.y = fmaxf(acc0.y, 0.f);
        acc0.z = fmaxf(acc0.z, 0.f); acc0.w = fmaxf(acc0.w, 0.f);
    }
    store_out(out, (size_t)warp * HD + lane * 4, acc0);
}

// ---------------- pool + head --------------------------------------------------
__global__ void __launch_bounds__(256) k_pool(const float* __restrict__ h,
                                              const int* __restrict__ batch, int n) {
    int warp = (blockIdx.x * blockDim.x + threadIdx.x) >> 5;
    int lane = threadIdx.x & 31;
    if (warp >= n) return;
    int b = batch[warp];
    float4 v = *(const float4*)(h + (size_t)warp * HD + lane * 4);
    float* p = &g_psum[b * HD + lane * 4];
    asm volatile("red.global.add.v4.f32 [%0], {%1,%2,%3,%4};"
                 :: "l"(p), "f"(v.x), "f"(v.y), "f"(v.z), "f"(v.w) : "memory");
    if (lane == 0) atomicAdd(&g_pcnt[b], 1.0f);
}

__global__ void k_final(const float* __restrict__ Wlin, const float* __restrict__ blin,
                        float* __restrict__ out) {
    int idx = blockIdx.x * blockDim.x + threadIdx.x;
    if (idx >= BGRAPH * CLS) return;
    int b = idx / CLS;
    int c = idx % CLS;
    float acc = 0.f;
#pragma unroll 8
    for (int k = 0; k < HD; k++) acc += g_psum[b * HD + k] * Wlin[k * CLS + c];
    float cnt = fmaxf(g_pcnt[b], 1.0f);
    out[idx] = acc / cnt + blin[c];
}

// ---------------- launch ------------------------------------------------------
extern "C" void kernel_launch(void* const* d_in, const int* in_sizes, int n_in,
                              void* d_out, int out_size) {
    const float* x    = (const float*)d_in[0];
    const int*   eidx = (const int*)d_in[1];
    const int*   batch= (const int*)d_in[2];
    const float* ew   = (const float*)d_in[3];
    const float* W1   = (const float*)d_in[4];
    const float* b1   = (const float*)d_in[5];
    const float* W2   = (const float*)d_in[6];
    const float* b2   = (const float*)d_in[7];
    const float* W3   = (const float*)d_in[8];
    const float* b3   = (const float*)d_in[9];
    const float* Wlin = (const float*)d_in[10];
    const float* blin = (const float*)d_in[11];
    float* out = (float*)d_out;

    int N = in_sizes[0] / HD;
    int E = in_sizes[1] / 2;
    const int* src = eidx;
    const int* dst = eidx + E;

    __half* th = nullptr; __half* hh = nullptr; float* h = nullptr;
    float2* e1 = nullptr; float2* e2 = nullptr;
    cudaGetSymbolAddress((void**)&th, g_th);
    cudaGetSymbolAddress((void**)&hh, g_hh);
    cudaGetSymbolAddress((void**)&h,  g_h);
    cudaGetSymbolAddress((void**)&e1, g_e1);
    cudaGetSymbolAddress((void**)&e2, g_e2);

    int eb = (E + 255) / 256;
    int nb = (N + 255) / 256;
    int wb = (N * 32 + 255) / 256;
    int gb = (N + 127) / 128;
    int sb = (N + 255) / 256;

    k_zero<<<256, 256>>>(N);
    k_deg<<<eb, 256>>>(dst, ew, E);
    k_dinv<<<nb, 256>>>(N);
    k_scan_partial<<<sb, 256>>>(N);
    k_scan_top<<<1, 256>>>(sb);
    k_scan_write<<<sb, 256>>>(N, E);
    k_scatter<<<eb, 256>>>(src, dst, ew, E);

    // layer 1: relu(A1 (x@W1) + b1), fill=2
    k_bperm<<<16, 256>>>(W1);
    k_gemm_tc<float><<<gb, 256>>>(x, th, N);
    k_agg<__half><<<wb, 256>>>(th, e1, b1, 2.0f, 1, hh, N);
    // layer 2: relu(A (h@W2) + b2), fill=1
    k_bperm<<<16, 256>>>(W2);
    k_gemm_tc<__half><<<gb, 256>>>(hh, th, N);
    k_agg<__half><<<wb, 256>>>(th, e2, b2, 1.0f, 1, hh, N);
    // layer 3: A (h@W3) + b3, fill=1
    k_bperm<<<16, 256>>>(W3);
    k_gemm_tc<__half><<<gb, 256>>>(hh, th, N);
    k_agg<float><<<wb, 256>>>(th, e2, b3, 1.0f, 0, h, N);

    k_pool<<<wb, 256>>>(h, batch, N);
    k_final<<<(BGRAPH * CLS + 127) / 128, 128>>>(Wlin, blin, out);
}

// round 5
// speedup vs baseline: 2.0846x; 1.2677x over previous
#include <cuda_runtime.h>
#include <cuda_fp16.h>
#include <math.h>
#include <stdint.h>

#define NN      50000
#define EE      1600000
#define HD      128
#define BGRAPH  512
#define CLS     10
#define SCAN_B  ((NN + 255) / 256)
#define FIXS    8388608.0f   // 2^23 fixed-point scale for packed degree

// ---------------- scratch (device globals; no allocs allowed) ----------------
__device__ unsigned long long g_cnt64[NN];  // hi32: count, lo32: weight*2^23
__device__ float  g_degb[NN];
__device__ int    g_rowptr[NN + 1];
__device__ int    g_woff[NN];
__device__ float  g_dinv1[NN];
__device__ float  g_dinv2[NN];
__device__ int    g_part[SCAN_B];
__device__ int    g_partscan[SCAN_B];
__device__ uint2  g_ed[EE];                 // (src, half2(norm1, norm2))
__device__ __half g_th[(size_t)NN * HD];    // GEMM output (fp16) -> agg gather
__device__ __half g_hh[(size_t)NN * HD];    // agg output (fp16)  -> next GEMM
__device__ uint2  g_bperm[3 * 8 * 16 * 32]; // W1,W2,W3 in mma B-fragment layout
__device__ float  g_psum[BGRAPH * HD];
__device__ float  g_pcnt[BGRAPH];

// ---------------- preprocessing ----------------------------------------------

__global__ void k_zero(int n) {
    int i = blockIdx.x * blockDim.x + threadIdx.x;
    int stride = gridDim.x * blockDim.x;
    for (int j = i; j < n; j += stride) g_cnt64[j] = 0ull;
    for (int j = i; j < BGRAPH * HD; j += stride) g_psum[j] = 0.f;
    for (int j = i; j < BGRAPH; j += stride) g_pcnt[j] = 0.f;
}

// one packed 64-bit atomic per edge: count++ and fixed-point weight sum
__global__ void k_deg(const int* __restrict__ dst, const float* __restrict__ ew, int E) {
    int i = blockIdx.x * blockDim.x + threadIdx.x;
    if (i >= E) return;
    int d = dst[i];
    unsigned long long v = (1ull << 32) |
        (unsigned long long)(unsigned int)__float2uint_rn(ew[i] * FIXS);
    atomicAdd(&g_cnt64[d], v);
}

// dinv + per-block count partials, fused
__global__ void k_scan_partial(int n) {
    __shared__ int s[256];
    int i = blockIdx.x * 256 + threadIdx.x;
    int c = 0;
    if (i < n) {
        unsigned long long v = g_cnt64[i];
        c = (int)(v >> 32);
        float db = (float)(unsigned int)(v & 0xffffffffull) * (1.0f / FIXS);
        g_degb[i]  = db;
        g_dinv1[i] = rsqrtf(db + 1.0f);
        g_dinv2[i] = rsqrtf(db + 2.0f);
    }
    s[threadIdx.x] = c;
    __syncthreads();
    for (int off = 128; off > 0; off >>= 1) {
        if (threadIdx.x < off) s[threadIdx.x] += s[threadIdx.x + off];
        __syncthreads();
    }
    if (threadIdx.x == 0) g_part[blockIdx.x] = s[0];
}

__global__ void k_scan_top(int nblocks) {
    __shared__ int s[256];
    int tid = threadIdx.x;
    int v = (tid < nblocks) ? g_part[tid] : 0;
    s[tid] = v;
    __syncthreads();
    for (int off = 1; off < 256; off <<= 1) {
        int u = (tid >= off) ? s[tid - off] : 0;
        __syncthreads();
        s[tid] += u;
        __syncthreads();
    }
    if (tid < nblocks) g_partscan[tid] = s[tid] - v;
}

__global__ void k_scan_write(int n, int E) {
    __shared__ int s[256];
    int tid = threadIdx.x;
    int i = blockIdx.x * 256 + tid;
    int c = (i < n) ? (int)(g_cnt64[i] >> 32) : 0;
    s[tid] = c;
    __syncthreads();
    for (int off = 1; off < 256; off <<= 1) {
        int u = (tid >= off) ? s[tid - off] : 0;
        __syncthreads();
        s[tid] += u;
        __syncthreads();
    }
    if (i < n) {
        int p = g_partscan[blockIdx.x] + s[tid] - c;
        g_rowptr[i] = p;
        g_woff[i]   = p;
    }
    if (blockIdx.x == 0 && tid == 0) g_rowptr[n] = E;
}

// scatter: one 8B store per edge carrying both norm variants (fp16)
__global__ void k_scatter(const int* __restrict__ src, const int* __restrict__ dst,
                          const float* __restrict__ ew, int E) {
    int e = blockIdx.x * blockDim.x + threadIdx.x;
    if (e >= E) return;
    int s = src[e];
    int d = dst[e];
    float w = ew[e];
    int pos = atomicAdd(&g_woff[d], 1);
    float n1 = g_dinv2[s] * w * g_dinv2[d];
    float n2 = g_dinv1[s] * w * g_dinv1[d];
    __half2 h = __floats2half2_rn(n1, n2);
    g_ed[pos] = make_uint2((unsigned)s, *(uint32_t*)&h);
}

// ---------------- tensor-core GEMM --------------------------------------------
// Pre-permute all three 128x128 weights into per-lane m16n8k16 B-fragment layout.
__global__ void k_bperm_all(const float* __restrict__ W1, const float* __restrict__ W2,
                            const float* __restrict__ W3) {
    int idx = blockIdx.x * blockDim.x + threadIdx.x;
    if (idx >= 3 * 4096) return;
    int l = idx >> 12;
    int r = idx & 4095;
    const float* W = (l == 0) ? W1 : (l == 1) ? W2 : W3;
    int lane = r & 31;
    int nt = (r >> 5) & 15;
    int kt = r >> 9;
    int k = kt * 16 + ((lane & 3) << 1);
    int n = nt * 8 + (lane >> 2);
    __half2 r0 = __floats2half2_rn(W[k * HD + n],       W[(k + 1) * HD + n]);
    __half2 r1 = __floats2half2_rn(W[(k + 8) * HD + n], W[(k + 9) * HD + n]);
    g_bperm[idx] = make_uint2(*(uint32_t*)&r0, *(uint32_t*)&r1);
}

__device__ __forceinline__ uint32_t ldA(const float* A, int r, int kc, int M) {
    if (r >= M) return 0u;
    float2 v = *(const float2*)(A + (size_t)r * HD + kc);
    __half2 h = __floats2half2_rn(v.x, v.y);
    return *(uint32_t*)&h;
}
__device__ __forceinline__ uint32_t ldA(const __half* A, int r, int kc, int M) {
    if (r >= M) return 0u;
    return *(const uint32_t*)(A + (size_t)r * HD + kc);
}

template <typename AT>
__global__ void __launch_bounds__(256) k_gemm_tc(const AT* __restrict__ A,
                                                 __half* __restrict__ C, int M,
                                                 int layer) {
    int lane = threadIdx.x & 31;
    int wid  = threadIdx.x >> 5;
    int wm   = wid & 3;
    int wn   = wid >> 2;
    int base = blockIdx.x * 128 + wm * 32 + (lane >> 2);
    int kc0  = (lane & 3) << 1;
    const uint2* bp = g_bperm + layer * 4096;

    float acc[2][8][4];
#pragma unroll
    for (int mt = 0; mt < 2; mt++)
#pragma unroll
        for (int nt = 0; nt < 8; nt++)
#pragma unroll
            for (int i = 0; i < 4; i++) acc[mt][nt][i] = 0.f;

#pragma unroll
    for (int kt = 0; kt < 8; kt++) {
        int kc = kt * 16 + kc0;
        uint32_t a[2][4];
#pragma unroll
        for (int mt = 0; mt < 2; mt++) {
            int r = base + mt * 16;
            a[mt][0] = ldA(A, r,     kc,     M);
            a[mt][1] = ldA(A, r + 8, kc,     M);
            a[mt][2] = ldA(A, r,     kc + 8, M);
            a[mt][3] = ldA(A, r + 8, kc + 8, M);
        }
#pragma unroll
        for (int nt = 0; nt < 8; nt++) {
            uint2 b = bp[(kt * 16 + wn * 8 + nt) * 32 + lane];
#pragma unroll
            for (int mt = 0; mt < 2; mt++) {
                asm volatile(
                    "mma.sync.aligned.m16n8k16.row.col.f32.f16.f16.f32 "
                    "{%0,%1,%2,%3}, {%4,%5,%6,%7}, {%8,%9}, {%0,%1,%2,%3};"
                    : "+f"(acc[mt][nt][0]), "+f"(acc[mt][nt][1]),
                      "+f"(acc[mt][nt][2]), "+f"(acc[mt][nt][3])
                    : "r"(a[mt][0]), "r"(a[mt][1]), "r"(a[mt][2]), "r"(a[mt][3]),
                      "r"(b.x), "r"(b.y));
            }
        }
    }

#pragma unroll
    for (int mt = 0; mt < 2; mt++) {
        int r = base + mt * 16;
#pragma unroll
        for (int nt = 0; nt < 8; nt++) {
            int n = wn * 64 + nt * 8 + ((lane & 3) << 1);
            if (r < M) {
                __half2 h = __floats2half2_rn(acc[mt][nt][0], acc[mt][nt][1]);
                *(uint32_t*)(C + (size_t)r * HD + n) = *(uint32_t*)&h;
            }
            if (r + 8 < M) {
                __half2 h = __floats2half2_rn(acc[mt][nt][2], acc[mt][nt][3]);
                *(uint32_t*)(C + (size_t)(r + 8) * HD + n) = *(uint32_t*)&h;
            }
        }
    }
}

// ---------------- aggregation --------------------------------------------------
// SEL=0 uses norm1 (layer 1), SEL=1 uses norm2 (layers 2,3)
template <int SEL>
__device__ __forceinline__ float edge_w(uint32_t hbits) {
    __half2 h = *(__half2*)&hbits;
    return SEL ? __high2float(h) : __low2float(h);
}

template <int SEL>
__device__ __forceinline__ float4 agg_row(const __half* __restrict__ t,
                                          const uint2* __restrict__ ed,
                                          const float* __restrict__ bias,
                                          float fill, int node, int lane) {
    int beg = g_rowptr[node];
    int end = g_rowptr[node + 1];
    float4 acc0 = make_float4(0.f, 0.f, 0.f, 0.f);
    float4 acc1 = make_float4(0.f, 0.f, 0.f, 0.f);
    int e = beg;
    for (; e + 3 < end; e += 4) {
        uint2 e0 = __ldg(&ed[e]);
        uint2 e1 = __ldg(&ed[e + 1]);
        uint2 e2 = __ldg(&ed[e + 2]);
        uint2 e3 = __ldg(&ed[e + 3]);
        uint2 r0 = __ldg((const uint2*)(t + (size_t)e0.x * HD) + lane);
        uint2 r1 = __ldg((const uint2*)(t + (size_t)e1.x * HD) + lane);
        uint2 r2 = __ldg((const uint2*)(t + (size_t)e2.x * HD) + lane);
        uint2 r3 = __ldg((const uint2*)(t + (size_t)e3.x * HD) + lane);
        float w0 = edge_w<SEL>(e0.y), w1 = edge_w<SEL>(e1.y);
        float w2 = edge_w<SEL>(e2.y), w3 = edge_w<SEL>(e3.y);
        float2 a, b;
        a = __half22float2(*(__half2*)&r0.x); b = __half22float2(*(__half2*)&r0.y);
        acc0.x += w0 * a.x; acc0.y += w0 * a.y; acc0.z += w0 * b.x; acc0.w += w0 * b.y;
        a = __half22float2(*(__half2*)&r1.x); b = __half22float2(*(__half2*)&r1.y);
        acc1.x += w1 * a.x; acc1.y += w1 * a.y; acc1.z += w1 * b.x; acc1.w += w1 * b.y;
        a = __half22float2(*(__half2*)&r2.x); b = __half22float2(*(__half2*)&r2.y);
        acc0.x += w2 * a.x; acc0.y += w2 * a.y; acc0.z += w2 * b.x; acc0.w += w2 * b.y;
        a = __half22float2(*(__half2*)&r3.x); b = __half22float2(*(__half2*)&r3.y);
        acc1.x += w3 * a.x; acc1.y += w3 * a.y; acc1.z += w3 * b.x; acc1.w += w3 * b.y;
    }
    for (; e < end; e++) {
        uint2 ei = __ldg(&ed[e]);
        uint2 r = __ldg((const uint2*)(t + (size_t)ei.x * HD) + lane);
        float w = edge_w<SEL>(ei.y);
        float2 a = __half22float2(*(__half2*)&r.x);
        float2 b = __half22float2(*(__half2*)&r.y);
        acc0.x += w * a.x; acc0.y += w * a.y; acc0.z += w * b.x; acc0.w += w * b.y;
    }
    acc0.x += acc1.x; acc0.y += acc1.y; acc0.z += acc1.z; acc0.w += acc1.w;
    float sn = fill / (g_degb[node] + fill);
    uint2 rs = __ldg((const uint2*)(t + (size_t)node * HD) + lane);
    float2 sa = __half22float2(*(__half2*)&rs.x);
    float2 sb = __half22float2(*(__half2*)&rs.y);
    acc0.x += sn * sa.x; acc0.y += sn * sa.y;
    acc0.z += sn * sb.x; acc0.w += sn * sb.y;
    float4 b4 = *(const float4*)(bias + lane * 4);
    acc0.x += b4.x; acc0.y += b4.y; acc0.z += b4.z; acc0.w += b4.w;
    return acc0;
}

// layers 1,2: relu + fp16 store
template <int SEL>
__global__ void __launch_bounds__(256) k_agg_relu(const __half* __restrict__ t,
                                                  const uint2* __restrict__ ed,
                                                  const float* __restrict__ bias,
                                                  float fill,
                                                  __half* __restrict__ out, int n) {
    int node = (blockIdx.x * blockDim.x + threadIdx.x) >> 5;
    int lane = threadIdx.x & 31;
    if (node >= n) return;
    float4 v = agg_row<SEL>(t, ed, bias, fill, node, lane);
    v.x = fmaxf(v.x, 0.f); v.y = fmaxf(v.y, 0.f);
    v.z = fmaxf(v.z, 0.f); v.w = fmaxf(v.w, 0.f);
    __half2 h0 = __floats2half2_rn(v.x, v.y);
    __half2 h1 = __floats2half2_rn(v.z, v.w);
    *(uint2*)(out + (size_t)node * HD + lane * 4) =
        make_uint2(*(uint32_t*)&h0, *(uint32_t*)&h1);
}

// layer 3: no relu, pool fused (red straight into graph sums)
__global__ void __launch_bounds__(256) k_agg_pool(const __half* __restrict__ t,
                                                  const uint2* __restrict__ ed,
                                                  const float* __restrict__ bias,
                                                  const int* __restrict__ batch, int n) {
    int node = (blockIdx.x * blockDim.x + threadIdx.x) >> 5;
    int lane = threadIdx.x & 31;
    if (node >= n) return;
    float4 v = agg_row<1>(t, ed, bias, 1.0f, node, lane);
    int b = batch[node];
    float* p = &g_psum[b * HD + lane * 4];
    asm volatile("red.global.add.v4.f32 [%0], {%1,%2,%3,%4};"
                 :: "l"(p), "f"(v.x), "f"(v.y), "f"(v.z), "f"(v.w) : "memory");
    if (lane == 0) atomicAdd(&g_pcnt[b], 1.0f);
}

// head
__global__ void k_final(const float* __restrict__ Wlin, const float* __restrict__ blin,
                        float* __restrict__ out) {
    int idx = blockIdx.x * blockDim.x + threadIdx.x;
    if (idx >= BGRAPH * CLS) return;
    int b = idx / CLS;
    int c = idx % CLS;
    float acc = 0.f;
#pragma unroll 8
    for (int k = 0; k < HD; k++) acc += g_psum[b * HD + k] * Wlin[k * CLS + c];
    float cnt = fmaxf(g_pcnt[b], 1.0f);
    out[idx] = acc / cnt + blin[c];
}

// ---------------- launch ------------------------------------------------------
extern "C" void kernel_launch(void* const* d_in, const int* in_sizes, int n_in,
                              void* d_out, int out_size) {
    const float* x    = (const float*)d_in[0];
    const int*   eidx = (const int*)d_in[1];
    const int*   batch= (const int*)d_in[2];
    const float* ew   = (const float*)d_in[3];
    const float* W1   = (const float*)d_in[4];
    const float* b1   = (const float*)d_in[5];
    const float* W2   = (const float*)d_in[6];
    const float* b2   = (const float*)d_in[7];
    const float* W3   = (const float*)d_in[8];
    const float* b3   = (const float*)d_in[9];
    const float* Wlin = (const float*)d_in[10];
    const float* blin = (const float*)d_in[11];
    float* out = (float*)d_out;

    int N = in_sizes[0] / HD;
    int E = in_sizes[1] / 2;
    const int* src = eidx;
    const int* dst = eidx + E;

    __half* th = nullptr; __half* hh = nullptr;
    uint2* ed = nullptr;
    cudaGetSymbolAddress((void**)&th, g_th);
    cudaGetSymbolAddress((void**)&hh, g_hh);
    cudaGetSymbolAddress((void**)&ed, g_ed);

    int eb = (E + 255) / 256;
    int wb = (N * 32 + 255) / 256;
    int gb = (N + 127) / 128;
    int sb = (N + 255) / 256;

    k_zero<<<256, 256>>>(N);
    k_bperm_all<<<48, 256>>>(W1, W2, W3);
    k_deg<<<eb, 256>>>(dst, ew, E);
    k_scan_partial<<<sb, 256>>>(N);
    k_scan_top<<<1, 256>>>(sb);
    k_scan_write<<<sb, 256>>>(N, E);
    k_scatter<<<eb, 256>>>(src, dst, ew, E);

    // layer 1: relu(A1 (x@W1) + b1), fill=2, norm1
    k_gemm_tc<float><<<gb, 256>>>(x, th, N, 0);
    k_agg_relu<0><<<wb, 256>>>(th, ed, b1, 2.0f, hh, N);
    // layer 2: relu(A (h@W2) + b2), fill=1, norm2
    k_gemm_tc<__half><<<gb, 256>>>(hh, th, N, 1);
    k_agg_relu<1><<<wb, 256>>>(th, ed, b2, 1.0f, hh, N);
    // layer 3: A (h@W3) + b3 with fused mean-pool accumulate
    k_gemm_tc<__half><<<gb, 256>>>(hh, th, N, 2);
    k_agg_pool<<<wb, 256>>>(th, ed, b3, batch, N);

    k_final<<<(BGRAPH * CLS + 127) / 128, 128>>>(Wlin, blin, out);
}